// round 3
// baseline (speedup 1.0000x reference)
#include <cuda_runtime.h>
#include <math.h>

#define NB 8
#define T  2048
#define E  1024
#define MT (NB*T)   // 16384 rows

// ---- scratch (device globals: allocation-free) ----
__device__ float g_Q[(size_t)MT*E];           // 64 MB
__device__ float g_K[(size_t)MT*E];           // 64 MB
__device__ float g_V[(size_t)MT*E];           // 64 MB
__device__ float g_S[(size_t)NB*T*T];         // 134 MB
__device__ float g_M [NB*T];
__device__ float g_Li[NB*T];

#define BM 128
#define BN 128
#define BK 16

// ============================================================
// Kernel 1: projection  Y = X @ W^T + bias   (NT gemm)
// X: [MT, E] row-major, W: [E(out), E(in)] row-major (K contiguous)
// which: 0->g_K, 1->g_Q, 2->g_V
// ============================================================
__global__ void __launch_bounds__(256) proj_kernel(
    const float* __restrict__ X, const float* __restrict__ W,
    const float* __restrict__ bias, int which)
{
    float* C = (which == 0) ? g_K : (which == 1) ? g_Q : g_V;
    __shared__ __align__(16) float As[BK][BM+4];
    __shared__ __align__(16) float Bs[BK][BN+4];
    const int tid = threadIdx.x;
    const int m0 = blockIdx.y * BM, n0 = blockIdx.x * BN;
    const int tx = tid & 15, ty = tid >> 4;
    const int ar = tid >> 2, ac = (tid & 3) << 2;

    float acc[8][8];
    #pragma unroll
    for (int i = 0; i < 8; i++)
        #pragma unroll
        for (int j = 0; j < 8; j++) acc[i][j] = 0.f;

    for (int k0 = 0; k0 < E; k0 += BK) {
        #pragma unroll
        for (int p = 0; p < 2; ++p) {
            int row = ar + p*64;
            float4 va = *(const float4*)(X + (size_t)(m0+row)*E + k0 + ac);
            As[ac+0][row]=va.x; As[ac+1][row]=va.y; As[ac+2][row]=va.z; As[ac+3][row]=va.w;
            float4 vb = *(const float4*)(W + (size_t)(n0+row)*E + k0 + ac);
            Bs[ac+0][row]=vb.x; Bs[ac+1][row]=vb.y; Bs[ac+2][row]=vb.z; Bs[ac+3][row]=vb.w;
        }
        __syncthreads();
        #pragma unroll
        for (int kk = 0; kk < BK; ++kk) {
            float a[8], bb[8];
            *(float4*)&a[0]  = *(const float4*)&As[kk][ty*8];
            *(float4*)&a[4]  = *(const float4*)&As[kk][ty*8+4];
            *(float4*)&bb[0] = *(const float4*)&Bs[kk][tx*8];
            *(float4*)&bb[4] = *(const float4*)&Bs[kk][tx*8+4];
            #pragma unroll
            for (int i = 0; i < 8; i++)
                #pragma unroll
                for (int j = 0; j < 8; j++) acc[i][j] = fmaf(a[i], bb[j], acc[i][j]);
        }
        __syncthreads();
    }
    #pragma unroll
    for (int i = 0; i < 8; i++) {
        int m = m0 + ty*8 + i;
        #pragma unroll
        for (int j = 0; j < 8; j += 4) {
            int n = n0 + tx*8 + j;
            float4 r;
            r.x = acc[i][j]   + bias[n];
            r.y = acc[i][j+1] + bias[n+1];
            r.z = acc[i][j+2] + bias[n+2];
            r.w = acc[i][j+3] + bias[n+3];
            *(float4*)(C + (size_t)m*E + n) = r;
        }
    }
}

// ============================================================
// Kernel 2: scores S[b,i,j] = Q[b,i,:] . K[b,j,:]  (NT gemm, triangle only)
// Upper-triangle tiles are skipped entirely (never read later).
// ============================================================
__global__ void __launch_bounds__(256) scores_kernel()
{
    if (blockIdx.x > blockIdx.y) return;   // whole tile is masked (j > i)
    const int b = blockIdx.z;
    const float* Q  = g_Q + (size_t)b*T*E;
    const float* Kp = g_K + (size_t)b*T*E;
    float*       S  = g_S + (size_t)b*T*T;

    __shared__ __align__(16) float As[BK][BM+4];
    __shared__ __align__(16) float Bs[BK][BN+4];
    const int tid = threadIdx.x;
    const int m0 = blockIdx.y * BM, n0 = blockIdx.x * BN;
    const int tx = tid & 15, ty = tid >> 4;
    const int ar = tid >> 2, ac = (tid & 3) << 2;

    float acc[8][8];
    #pragma unroll
    for (int i = 0; i < 8; i++)
        #pragma unroll
        for (int j = 0; j < 8; j++) acc[i][j] = 0.f;

    for (int k0 = 0; k0 < E; k0 += BK) {
        #pragma unroll
        for (int p = 0; p < 2; ++p) {
            int row = ar + p*64;
            float4 va = *(const float4*)(Q  + (size_t)(m0+row)*E + k0 + ac);
            As[ac+0][row]=va.x; As[ac+1][row]=va.y; As[ac+2][row]=va.z; As[ac+3][row]=va.w;
            float4 vb = *(const float4*)(Kp + (size_t)(n0+row)*E + k0 + ac);
            Bs[ac+0][row]=vb.x; Bs[ac+1][row]=vb.y; Bs[ac+2][row]=vb.z; Bs[ac+3][row]=vb.w;
        }
        __syncthreads();
        #pragma unroll
        for (int kk = 0; kk < BK; ++kk) {
            float a[8], bb[8];
            *(float4*)&a[0]  = *(const float4*)&As[kk][ty*8];
            *(float4*)&a[4]  = *(const float4*)&As[kk][ty*8+4];
            *(float4*)&bb[0] = *(const float4*)&Bs[kk][tx*8];
            *(float4*)&bb[4] = *(const float4*)&Bs[kk][tx*8+4];
            #pragma unroll
            for (int i = 0; i < 8; i++)
                #pragma unroll
                for (int j = 0; j < 8; j++) acc[i][j] = fmaf(a[i], bb[j], acc[i][j]);
        }
        __syncthreads();
    }
    #pragma unroll
    for (int i = 0; i < 8; i++) {
        int m = m0 + ty*8 + i;
        #pragma unroll
        for (int j = 0; j < 8; j += 4) {
            int n = n0 + tx*8 + j;
            *(float4*)(S + (size_t)m*T + n) =
                make_float4(acc[i][j], acc[i][j+1], acc[i][j+2], acc[i][j+3]);
        }
    }
}

// ============================================================
// Kernel 3: per-column (key j) stats over i >= j: max m_j, sumexp -> 1/l_j
// softmax is over the QUERY axis (faithful quirk).
// ============================================================
__global__ void __launch_bounds__(256) colstats_kernel()
{
    const int b = blockIdx.y;
    const int j = blockIdx.x * 256 + threadIdx.x;
    const float* S = g_S + (size_t)b*T*T;
    float m = -INFINITY, l = 0.f;
    for (int i = j; i < T; ++i) {
        float v = S[(size_t)i*T + j];
        if (v <= m) {
            l += expf(v - m);
        } else {
            l = l * expf(m - v) + 1.f;
            m = v;
        }
    }
    g_M [b*T + j] = m;
    g_Li[b*T + j] = 1.f / l;
}

// ============================================================
// Kernel 4: O[b,i,:] = sum_{j<=i} exp(S[i,j]-m_j)*linv_j * V[b,j,:]
// NN gemm; A tile (P) is built from S at load time; k-loop stops at diagonal.
// ============================================================
__global__ void __launch_bounds__(256) out_gemm(float* __restrict__ Out)
{
    const int b = blockIdx.z;
    const float* S  = g_S + (size_t)b*T*T;
    const float* V  = g_V + (size_t)b*T*E;
    const float* Mv = g_M  + b*T;
    const float* Li = g_Li + b*T;
    float*       O  = Out + (size_t)b*T*E;

    __shared__ __align__(16) float As[BK][BM+4];
    __shared__ __align__(16) float Bs[BK][BN+4];
    const int tid = threadIdx.x;
    const int m0 = blockIdx.y * BM, n0 = blockIdx.x * BN;
    const int tx = tid & 15, ty = tid >> 4;
    const int ar = tid >> 2, ac = (tid & 3) << 2;
    const int br = tid >> 5, bc = (tid & 31) << 2;

    float acc[8][8];
    #pragma unroll
    for (int i = 0; i < 8; i++)
        #pragma unroll
        for (int j = 0; j < 8; j++) acc[i][j] = 0.f;

    const int nkt = m0/BK + BM/BK;   // j-tiles up to and including the diagonal
    for (int kt = 0; kt < nkt; ++kt) {
        const int k0 = kt * BK;
        #pragma unroll
        for (int p = 0; p < 2; ++p) {
            int row = ar + p*64;
            int i = m0 + row;
            float4 s4 = *(const float4*)(S + (size_t)i*T + k0 + ac);
            float sv[4] = {s4.x, s4.y, s4.z, s4.w};
            #pragma unroll
            for (int c = 0; c < 4; ++c) {
                int j = k0 + ac + c;
                As[ac+c][row] = (j <= i) ? expf(sv[c] - Mv[j]) * Li[j] : 0.f;
            }
            int r = br + p*8;
            *(float4*)&Bs[r][bc] = *(const float4*)(V + (size_t)(k0+r)*E + n0 + bc);
        }
        __syncthreads();
        #pragma unroll
        for (int kk = 0; kk < BK; ++kk) {
            float a[8], bb[8];
            *(float4*)&a[0]  = *(const float4*)&As[kk][ty*8];
            *(float4*)&a[4]  = *(const float4*)&As[kk][ty*8+4];
            *(float4*)&bb[0] = *(const float4*)&Bs[kk][tx*8];
            *(float4*)&bb[4] = *(const float4*)&Bs[kk][tx*8+4];
            #pragma unroll
            for (int i = 0; i < 8; i++)
                #pragma unroll
                for (int j = 0; j < 8; j++) acc[i][j] = fmaf(a[i], bb[j], acc[i][j]);
        }
        __syncthreads();
    }
    #pragma unroll
    for (int i = 0; i < 8; i++) {
        int m = m0 + ty*8 + i;
        #pragma unroll
        for (int j = 0; j < 8; j += 4) {
            int n = n0 + tx*8 + j;
            *(float4*)(O + (size_t)m*E + n) =
                make_float4(acc[i][j], acc[i][j+1], acc[i][j+2], acc[i][j+3]);
        }
    }
}

// ============================================================
extern "C" void kernel_launch(void* const* d_in, const int* in_sizes, int n_in,
                              void* d_out, int out_size)
{
    const float* x_emb = (const float*)d_in[0];
    // d_in[1] = token ids (unused by reference math)
    const float* Wk = (const float*)d_in[2];
    const float* bk = (const float*)d_in[3];
    const float* Wq = (const float*)d_in[4];
    const float* bq = (const float*)d_in[5];
    const float* Wv = (const float*)d_in[6];
    const float* bv = (const float*)d_in[7];
    float* out = (float*)d_out;

    dim3 blk(256);
    dim3 gproj(E/BN, MT/BM);          // (8, 128)
    proj_kernel<<<gproj, blk>>>(x_emb, Wk, bk, 0);
    proj_kernel<<<gproj, blk>>>(x_emb, Wq, bq, 1);
    proj_kernel<<<gproj, blk>>>(x_emb, Wv, bv, 2);

    dim3 gsc(T/BN, T/BM, NB);         // (16, 16, 8)
    scores_kernel<<<gsc, blk>>>();

    dim3 gcs(T/256, NB);              // (8, 8)
    colstats_kernel<<<gcs, blk>>>();

    dim3 gout(E/BN, T/BM, NB);        // (8, 16, 8)
    out_gemm<<<gout, blk>>>(out);
}

// round 5
// speedup vs baseline: 1.5256x; 1.5256x over previous
#include <cuda_runtime.h>
#include <math.h>
#include <stdint.h>

#define NB 8
#define T  2048
#define E  1024
#define MT (NB*T)

// ------------------------- scratch (device globals) -------------------------
__device__ float g_Xh[(size_t)MT*E], g_Xl[(size_t)MT*E];
__device__ float g_Whk[(size_t)E*E], g_Wlk[(size_t)E*E];
__device__ float g_Whq[(size_t)E*E], g_Wlq[(size_t)E*E];
__device__ float g_Whv[(size_t)E*E], g_Wlv[(size_t)E*E];
__device__ float g_Qh[(size_t)MT*E], g_Ql[(size_t)MT*E];
__device__ float g_Kh[(size_t)MT*E], g_Kl[(size_t)MT*E];
__device__ float g_Vth[(size_t)NB*E*T], g_Vtl[(size_t)NB*E*T];   // [b][f][t]
__device__ float g_S [(size_t)NB*T*T];
__device__ float g_Ph[(size_t)NB*T*T];
__device__ float g_M[NB*T], g_Li[NB*T];

// ------------------------- helpers -------------------------
__device__ __forceinline__ uint32_t smem_u32(const void* p) {
    uint32_t a;
    asm("{ .reg .u64 t; cvta.to.shared.u64 t, %1; cvt.u32.u64 %0, t; }" : "=r"(a) : "l"(p));
    return a;
}
__device__ __forceinline__ float tf32_rna(float x) {
    uint32_t u; asm("cvt.rna.tf32.f32 %0, %1;" : "=r"(u) : "f"(x));
    return __uint_as_float(u);
}
__device__ __forceinline__ void cpa16(uint32_t dst, const float* src) {
    asm volatile("cp.async.cg.shared.global [%0], [%1], 16;" :: "r"(dst), "l"(src) : "memory");
}
__device__ __forceinline__ void cpa_commit() { asm volatile("cp.async.commit_group;" ::: "memory"); }
template<int N> __device__ __forceinline__ void cpa_wait() {
    asm volatile("cp.async.wait_group %0;" :: "n"(N) : "memory");
}
__device__ __forceinline__ void mma8(float* d, uint32_t a0, uint32_t a1, uint32_t a2, uint32_t a3,
                                     uint32_t b0, uint32_t b1) {
    asm volatile("mma.sync.aligned.m16n8k8.row.col.f32.tf32.tf32.f32 "
                 "{%0,%1,%2,%3},{%4,%5,%6,%7},{%8,%9},{%0,%1,%2,%3};"
                 : "+f"(d[0]), "+f"(d[1]), "+f"(d[2]), "+f"(d[3])
                 : "r"(a0), "r"(a1), "r"(a2), "r"(a3), "r"(b0), "r"(b1));
}

// ------------------------- tf32x3 mma.sync GEMM -------------------------
// D[m,n] = sum_k A[m,k]*B[n,k] (NT, both K-major). 128x128 tile, BK=32.
// MODE 0: proj Q/K (+bias, hi/lo split row-major store)
// MODE 1: proj V   (+bias, hi/lo split TRANSPOSED store -> Vt[b][f][t])
// MODE 2: scores   (triangle grid, fp32 store to S)
// MODE 3: out      (A=P single tf32, B=Vt hi/lo; 2 passes; k stops at diagonal)
#define NSTAGE 3
#define STAGE_F (4*4096)                 // 4 slots x (128x32) floats
#define SMEM_BYTES (NSTAGE*STAGE_F*4)    // 196608

template<int MODE>
__global__ void __launch_bounds__(256, 1) gemm_mma(
    const float* __restrict__ pAh, const float* __restrict__ pAl,
    const float* __restrict__ pBh, const float* __restrict__ pBl,
    float* __restrict__ out0, float* __restrict__ out1,
    const float* __restrict__ bias)
{
    if (MODE == 2 && blockIdx.x > blockIdx.y) return;

    extern __shared__ float smf[];
    const uint32_t sb = smem_u32(smf);
    const int tid = threadIdx.x;
    const int lane = tid & 31, warp = tid >> 5;
    const int wm = warp >> 2, wn = warp & 3;        // 2 x 4 warp grid
    const int g = lane >> 2, c = lane & 3;
    const int b = blockIdx.z;
    const int m0 = blockIdx.y * 128, n0 = blockIdx.x * 128;

    int ld, nchunks;
    const float *Ah_, *Al_, *Bh_, *Bl_;
    if (MODE <= 1) {
        ld = E; nchunks = E/32;
        Ah_ = pAh + (size_t)m0*E;  Al_ = pAl + (size_t)m0*E;
        Bh_ = pBh + (size_t)n0*E;  Bl_ = pBl + (size_t)n0*E;
    } else if (MODE == 2) {
        ld = E; nchunks = E/32;
        Ah_ = pAh + (size_t)(b*T + m0)*E;  Al_ = pAl + (size_t)(b*T + m0)*E;
        Bh_ = pBh + (size_t)(b*T + n0)*E;  Bl_ = pBl + (size_t)(b*T + n0)*E;
    } else {
        ld = T; nchunks = m0/32 + 4;                 // up to and including diagonal tile
        Ah_ = pAh + (size_t)b*T*T + (size_t)m0*T;  Al_ = Ah_;   // unused
        Bh_ = pBh + ((size_t)b*E + n0)*T;  Bl_ = pBl + ((size_t)b*E + n0)*T;
    }

    const int NT = (MODE == 3) ? 3 : 4;
    auto fill = [&](int ck) {
        const int stg = ck % NSTAGE;
        const int k0 = ck * 32;
        for (int i = tid; i < NT*1024; i += 256) {
            int tile = i >> 10, rem = i & 1023;
            int r = rem >> 3, k4 = rem & 7;
            int slot = (MODE == 3) ? ((tile == 0) ? 0 : tile + 1) : tile;
            const float* src =
                (slot == 0 ? Ah_ : slot == 1 ? Al_ : slot == 2 ? Bh_ : Bl_)
                + (size_t)r*ld + k0 + k4*4;
            uint32_t dst = sb + (uint32_t)(stg*STAGE_F + slot*4096
                                           + r*32 + ((k4 ^ (r & 7)) << 2)) * 4u;
            cpa16(dst, src);
        }
        cpa_commit();
    };

    float acc[4][4][4];
    #pragma unroll
    for (int mi = 0; mi < 4; mi++)
        #pragma unroll
        for (int ni = 0; ni < 4; ni++)
            #pragma unroll
            for (int q = 0; q < 4; q++) acc[mi][ni][q] = 0.f;

    fill(0);
    fill(1);

    for (int ck = 0; ck < nchunks; ck++) {
        if (ck + 1 < nchunks) cpa_wait<1>(); else cpa_wait<0>();
        __syncthreads();
        if (ck + 2 < nchunks) fill(ck + 2);

        const float* S0 = smf + (ck % NSTAGE) * STAGE_F;
        const uint32_t* Sah = (const uint32_t*)(S0);
        const uint32_t* Sal = (const uint32_t*)(S0 + 4096);
        const uint32_t* Sbh = (const uint32_t*)(S0 + 8192);
        const uint32_t* Sbl = (const uint32_t*)(S0 + 12288);

        #pragma unroll
        for (int ks = 0; ks < 4; ks++) {
            const int p0 = ((2*ks)     ^ g)*4 + c;
            const int p1 = ((2*ks + 1) ^ g)*4 + c;
            uint32_t ah[4][4], al[4][4], bh[4][2], bl[4][2];
            #pragma unroll
            for (int mi = 0; mi < 4; mi++) {
                int r0 = (wm*64 + mi*16 + g) * 32;
                ah[mi][0] = Sah[r0 + p0];       ah[mi][1] = Sah[r0 + 256 + p0];
                ah[mi][2] = Sah[r0 + p1];       ah[mi][3] = Sah[r0 + 256 + p1];
                if (MODE != 3) {
                    al[mi][0] = Sal[r0 + p0];   al[mi][1] = Sal[r0 + 256 + p0];
                    al[mi][2] = Sal[r0 + p1];   al[mi][3] = Sal[r0 + 256 + p1];
                }
            }
            #pragma unroll
            for (int ni = 0; ni < 4; ni++) {
                int rn = (wn*32 + ni*8 + g) * 32;
                bh[ni][0] = Sbh[rn + p0];  bh[ni][1] = Sbh[rn + p1];
                bl[ni][0] = Sbl[rn + p0];  bl[ni][1] = Sbl[rn + p1];
            }
            #pragma unroll
            for (int mi = 0; mi < 4; mi++)
                #pragma unroll
                for (int ni = 0; ni < 4; ni++) {
                    mma8(acc[mi][ni], ah[mi][0], ah[mi][1], ah[mi][2], ah[mi][3], bh[ni][0], bh[ni][1]);
                    mma8(acc[mi][ni], ah[mi][0], ah[mi][1], ah[mi][2], ah[mi][3], bl[ni][0], bl[ni][1]);
                    if (MODE != 3)
                        mma8(acc[mi][ni], al[mi][0], al[mi][1], al[mi][2], al[mi][3], bh[ni][0], bh[ni][1]);
                }
        }
    }

    // ------------- epilogue -------------
    #pragma unroll
    for (int mi = 0; mi < 4; mi++) {
        #pragma unroll
        for (int ni = 0; ni < 4; ni++) {
            const int r1 = m0 + wm*64 + mi*16 + g, r2 = r1 + 8;
            const int col = n0 + wn*32 + ni*8 + 2*c;
            float* a = acc[mi][ni];
            if (MODE == 0) {
                float2 bs = *(const float2*)(bias + col);
                float y0 = a[0] + bs.x, y1 = a[1] + bs.y;
                float y2 = a[2] + bs.x, y3 = a[3] + bs.y;
                float h0 = tf32_rna(y0), h1 = tf32_rna(y1);
                float h2 = tf32_rna(y2), h3 = tf32_rna(y3);
                *(float2*)(out0 + (size_t)r1*E + col) = make_float2(h0, h1);
                *(float2*)(out1 + (size_t)r1*E + col) = make_float2(y0 - h0, y1 - h1);
                *(float2*)(out0 + (size_t)r2*E + col) = make_float2(h2, h3);
                *(float2*)(out1 + (size_t)r2*E + col) = make_float2(y2 - h2, y3 - h3);
            } else if (MODE == 1) {
                float2 bs = *(const float2*)(bias + col);
                float y0 = a[0] + bs.x, y1 = a[1] + bs.y;
                float y2 = a[2] + bs.x, y3 = a[3] + bs.y;
                float h0 = tf32_rna(y0), h1 = tf32_rna(y1);
                float h2 = tf32_rna(y2), h3 = tf32_rna(y3);
                const size_t bo = (size_t)(m0 / T) * E * T;
                const int tl1 = (m0 % T) + wm*64 + mi*16 + g, tl2 = tl1 + 8;
                out0[bo + (size_t)col*T     + tl1] = h0;  out1[bo + (size_t)col*T     + tl1] = y0 - h0;
                out0[bo + (size_t)(col+1)*T + tl1] = h1;  out1[bo + (size_t)(col+1)*T + tl1] = y1 - h1;
                out0[bo + (size_t)col*T     + tl2] = h2;  out1[bo + (size_t)col*T     + tl2] = y2 - h2;
                out0[bo + (size_t)(col+1)*T + tl2] = h3;  out1[bo + (size_t)(col+1)*T + tl2] = y3 - h3;
            } else if (MODE == 2) {
                float* Sb = out0 + (size_t)b*T*T;
                *(float2*)(Sb + (size_t)r1*T + col) = make_float2(a[0], a[1]);
                *(float2*)(Sb + (size_t)r2*T + col) = make_float2(a[2], a[3]);
            } else {
                float* Ob = out0 + (size_t)b*T*E;
                *(float2*)(Ob + (size_t)r1*E + col) = make_float2(a[0], a[1]);
                *(float2*)(Ob + (size_t)r2*E + col) = make_float2(a[2], a[3]);
            }
        }
    }
}

// ------------------------- elementwise kernels -------------------------
__global__ void __launch_bounds__(256) splitk(
    const float* __restrict__ src, float* __restrict__ dh, float* __restrict__ dl, int n4)
{
    int i = blockIdx.x * 256 + threadIdx.x;
    if (i >= n4) return;
    float4 v = ((const float4*)src)[i];
    float4 h, l;
    h.x = tf32_rna(v.x); l.x = v.x - h.x;
    h.y = tf32_rna(v.y); l.y = v.y - h.y;
    h.z = tf32_rna(v.z); l.z = v.z - h.z;
    h.w = tf32_rna(v.w); l.w = v.w - h.w;
    ((float4*)dh)[i] = h;
    ((float4*)dl)[i] = l;
}

// per-key-column j stats over i>=j (softmax over QUERY axis quirk)
__global__ void __launch_bounds__(256) colstats()
{
    const int bb = blockIdx.y;
    const int j0 = blockIdx.x * 32;
    const int c = threadIdx.x & 31, r = threadIdx.x >> 5;
    const int j = j0 + c;
    const float* S = g_S + (size_t)bb*T*T;
    float m = -INFINITY, l = 0.f;
    for (int i = j0 + r; i < T; i += 8) {
        float v = S[(size_t)i*T + j];
        if (i >= j) {
            if (v <= m) l += expf(v - m);
            else { l = l * expf(m - v) + 1.f; m = v; }
        }
    }
    __shared__ float sm_[8][33], sl_[8][33];
    sm_[r][c] = m; sl_[r][c] = l;
    __syncthreads();
    if (r == 0) {
        float M = m, L = l;
        #pragma unroll
        for (int rr = 1; rr < 8; rr++) {
            float m2 = sm_[rr][c], l2 = sl_[rr][c];
            if (m2 > M) { L = L * expf(M - m2) + l2; M = m2; }
            else if (l2 > 0.f) L += l2 * expf(m2 - M);
        }
        g_M [bb*T + j] = M;
        g_Li[bb*T + j] = 1.f / L;
    }
}

// P[i,j] = exp(S[i,j]-m_j)*linv_j for j<=i else 0 (tf32-rounded)
__global__ void __launch_bounds__(256) psplit()
{
    const int jt = blockIdx.x, it = blockIdx.y;
    if (jt > it) return;
    const int bb = blockIdx.z;
    const size_t base = (size_t)bb*T*T;
    const int i0 = it*128, j0 = jt*128;
    for (int idx = threadIdx.x; idx < 128*32; idx += 256) {
        int rr = idx >> 5, c4 = idx & 31;
        int i = i0 + rr, j = j0 + c4*4;
        float4 s = *(const float4*)(g_S + base + (size_t)i*T + j);
        float sv[4] = {s.x, s.y, s.z, s.w};
        float h[4];
        #pragma unroll
        for (int q = 0; q < 4; q++) {
            int jj = j + q;
            float p = (jj <= i) ? expf(sv[q] - g_M[bb*T + jj]) * g_Li[bb*T + jj] : 0.f;
            h[q] = tf32_rna(p);
        }
        *(float4*)(g_Ph + base + (size_t)i*T + j) = make_float4(h[0], h[1], h[2], h[3]);
    }
}

// ------------------------- host -------------------------
extern "C" void kernel_launch(void* const* d_in, const int* in_sizes, int n_in,
                              void* d_out, int out_size)
{
    const float* x_emb = (const float*)d_in[0];
    const float* Wk = (const float*)d_in[2];
    const float* bk = (const float*)d_in[3];
    const float* Wq = (const float*)d_in[4];
    const float* bq = (const float*)d_in[5];
    const float* Wv = (const float*)d_in[6];
    const float* bv = (const float*)d_in[7];
    float* out = (float*)d_out;

    void *Xh,*Xl,*Whk,*Wlk,*Whq,*Wlq,*Whv,*Wlv,*Qh,*Ql,*Kh,*Kl,*Vth,*Vtl,*Sp,*Ph;
    cudaGetSymbolAddress(&Xh, g_Xh);   cudaGetSymbolAddress(&Xl, g_Xl);
    cudaGetSymbolAddress(&Whk, g_Whk); cudaGetSymbolAddress(&Wlk, g_Wlk);
    cudaGetSymbolAddress(&Whq, g_Whq); cudaGetSymbolAddress(&Wlq, g_Wlq);
    cudaGetSymbolAddress(&Whv, g_Whv); cudaGetSymbolAddress(&Wlv, g_Wlv);
    cudaGetSymbolAddress(&Qh, g_Qh);   cudaGetSymbolAddress(&Ql, g_Ql);
    cudaGetSymbolAddress(&Kh, g_Kh);   cudaGetSymbolAddress(&Kl, g_Kl);
    cudaGetSymbolAddress(&Vth, g_Vth); cudaGetSymbolAddress(&Vtl, g_Vtl);
    cudaGetSymbolAddress(&Sp, g_S);    cudaGetSymbolAddress(&Ph, g_Ph);

    cudaFuncSetAttribute(gemm_mma<0>, cudaFuncAttributeMaxDynamicSharedMemorySize, SMEM_BYTES);
    cudaFuncSetAttribute(gemm_mma<1>, cudaFuncAttributeMaxDynamicSharedMemorySize, SMEM_BYTES);
    cudaFuncSetAttribute(gemm_mma<2>, cudaFuncAttributeMaxDynamicSharedMemorySize, SMEM_BYTES);
    cudaFuncSetAttribute(gemm_mma<3>, cudaFuncAttributeMaxDynamicSharedMemorySize, SMEM_BYTES);

    // 1. tf32 hi/lo splits
    splitk<<<(MT*E/4 + 255)/256, 256>>>(x_emb, (float*)Xh, (float*)Xl, MT*E/4);
    splitk<<<(E*E/4 + 255)/256, 256>>>(Wk, (float*)Whk, (float*)Wlk, E*E/4);
    splitk<<<(E*E/4 + 255)/256, 256>>>(Wq, (float*)Whq, (float*)Wlq, E*E/4);
    splitk<<<(E*E/4 + 255)/256, 256>>>(Wv, (float*)Whv, (float*)Wlv, E*E/4);

    // 2. projections
    dim3 gp(E/128, MT/128);
    gemm_mma<0><<<gp, 256, SMEM_BYTES>>>((float*)Xh, (float*)Xl, (float*)Whq, (float*)Wlq,
                                         (float*)Qh, (float*)Ql, bq);
    gemm_mma<0><<<gp, 256, SMEM_BYTES>>>((float*)Xh, (float*)Xl, (float*)Whk, (float*)Wlk,
                                         (float*)Kh, (float*)Kl, bk);
    gemm_mma<1><<<gp, 256, SMEM_BYTES>>>((float*)Xh, (float*)Xl, (float*)Whv, (float*)Wlv,
                                         (float*)Vth, (float*)Vtl, bv);

    // 3. scores (lower triangle only)
    dim3 gs(T/128, T/128, NB);
    gemm_mma<2><<<gs, 256, SMEM_BYTES>>>((float*)Qh, (float*)Ql, (float*)Kh, (float*)Kl,
                                         (float*)Sp, nullptr, nullptr);

    // 4. column softmax stats + P build
    dim3 gc(T/32, NB);
    colstats<<<gc, 256>>>();
    psplit<<<dim3(T/128, T/128, NB), 256>>>();

    // 5. output gemm
    dim3 go(E/128, T/128, NB);
    gemm_mma<3><<<go, 256, SMEM_BYTES>>>((float*)Ph, (float*)Ph, (float*)Vth, (float*)Vtl,
                                         out, nullptr, nullptr);
}

// round 6
// speedup vs baseline: 1.8143x; 1.1892x over previous
#include <cuda_runtime.h>
#include <math.h>
#include <stdint.h>

#define NB 8
#define T  2048
#define E  1024
#define MT (NB*T)

// ------------------------- scratch (device globals) -------------------------
__device__ float g_Xh[(size_t)MT*E], g_Xl[(size_t)MT*E];
__device__ float g_Whk[(size_t)E*E], g_Wlk[(size_t)E*E];
__device__ float g_Whq[(size_t)E*E], g_Wlq[(size_t)E*E];
__device__ float g_Whv[(size_t)E*E], g_Wlv[(size_t)E*E];
__device__ float g_Qh[(size_t)MT*E], g_Ql[(size_t)MT*E];
__device__ float g_Kh[(size_t)MT*E], g_Kl[(size_t)MT*E];
__device__ float g_Vth[(size_t)NB*E*T];                     // [b][f][t], tf32-rounded
__device__ float g_S [(size_t)NB*T*T];
__device__ float g_Ph[(size_t)NB*T*T];
__device__ float g_M[NB*T], g_Li[NB*T];

// ------------------------- helpers -------------------------
__device__ __forceinline__ uint32_t smem_u32(const void* p) {
    uint32_t a;
    asm("{ .reg .u64 t; cvta.to.shared.u64 t, %1; cvt.u32.u64 %0, t; }" : "=r"(a) : "l"(p));
    return a;
}
__device__ __forceinline__ float tf32_rna(float x) {
    uint32_t u; asm("cvt.rna.tf32.f32 %0, %1;" : "=r"(u) : "f"(x));
    return __uint_as_float(u);
}
__device__ __forceinline__ void cpa16(uint32_t dst, const float* src) {
    asm volatile("cp.async.cg.shared.global [%0], [%1], 16;" :: "r"(dst), "l"(src) : "memory");
}
__device__ __forceinline__ void cpa_commit() { asm volatile("cp.async.commit_group;" ::: "memory"); }
template<int N> __device__ __forceinline__ void cpa_wait() {
    asm volatile("cp.async.wait_group %0;" :: "n"(N) : "memory");
}
__device__ __forceinline__ void mma8(float* d, uint32_t a0, uint32_t a1, uint32_t a2, uint32_t a3,
                                     uint32_t b0, uint32_t b1) {
    asm volatile("mma.sync.aligned.m16n8k8.row.col.f32.tf32.tf32.f32 "
                 "{%0,%1,%2,%3},{%4,%5,%6,%7},{%8,%9},{%0,%1,%2,%3};"
                 : "+f"(d[0]), "+f"(d[1]), "+f"(d[2]), "+f"(d[3])
                 : "r"(a0), "r"(a1), "r"(a2), "r"(a3), "r"(b0), "r"(b1));
}

// ------------------------- tf32 mma.sync GEMM, 256x128x32 tile -------------------------
// D[m,n] = sum_k A[m,k]*B[n,k] (NT, both K-major). 512 threads, 16 warps (4x4), warp 64x32.
// MODE 0: proj Q/K, 3-pass (hh+hl+lh), +bias, hi/lo split row-major store
// MODE 1: proj V,   1-pass, +bias, tf32-rounded TRANSPOSED store -> Vt[b][f][t]
// MODE 2: scores,   3-pass, triangle grid, fp32 store to S
// MODE 3: out,      1-pass (A=Ph tf32, B=Vt tf32), k stops past diagonal
#define STAGE_F 24576                    // Ah 8192 | Al 8192 | Bh 4096 | Bl 4096 floats
#define SMEM_BYTES (2*STAGE_F*4)         // 196608

template<int MODE>
__global__ void __launch_bounds__(512, 1) gemm_mma(
    const float* __restrict__ pAh, const float* __restrict__ pAl,
    const float* __restrict__ pBh, const float* __restrict__ pBl,
    float* __restrict__ out0, float* __restrict__ out1,
    const float* __restrict__ bias)
{
    constexpr int NPASS = (MODE == 0 || MODE == 2) ? 3 : 1;
    const int m0 = blockIdx.y * 256, n0 = blockIdx.x * 128;
    if (MODE == 2 && n0 >= m0 + 256) return;   // tile fully above diagonal

    extern __shared__ float smf[];
    const uint32_t sb = smem_u32(smf);
    const int tid = threadIdx.x;
    const int lane = tid & 31, warp = tid >> 5;
    const int wm = warp >> 2, wn = warp & 3;         // 4 x 4 warp grid
    const int g = lane >> 2, c = lane & 3;
    const int b = blockIdx.z;

    int ld, nchunks;
    const float *Ah_, *Al_, *Bh_, *Bl_;
    if (MODE <= 1) {
        ld = E; nchunks = E/32;
        Ah_ = pAh + (size_t)m0*E;  Al_ = pAl + (size_t)m0*E;
        Bh_ = pBh + (size_t)n0*E;  Bl_ = pBl + (size_t)n0*E;
    } else if (MODE == 2) {
        ld = E; nchunks = E/32;
        Ah_ = pAh + (size_t)(b*T + m0)*E;  Al_ = pAl + (size_t)(b*T + m0)*E;
        Bh_ = pBh + (size_t)(b*T + n0)*E;  Bl_ = pBl + (size_t)(b*T + n0)*E;
    } else {
        ld = T; nchunks = m0/32 + 8;                  // k up to m0+256 (P zero-padded)
        Ah_ = pAh + (size_t)b*T*T + (size_t)m0*T;  Al_ = Ah_;
        Bh_ = pBh + ((size_t)b*E + n0)*T;          Bl_ = Bh_;
    }

    auto fill = [&](int ck) {
        const int stg = ck & 1;
        const int k0 = ck * 32;
        const int total = (NPASS == 3) ? 6144 : 3072;
        for (int i = tid; i < total; i += 512) {
            const float* srcb; int row; uint32_t soff;
            if (NPASS == 3) {
                if (i < 2048)      { srcb = Ah_; row = i >> 3;          soff = 0; }
                else if (i < 4096) { srcb = Al_; row = (i-2048) >> 3;   soff = 8192; }
                else if (i < 5120) { srcb = Bh_; row = (i-4096) >> 3;   soff = 16384; }
                else               { srcb = Bl_; row = (i-5120) >> 3;   soff = 20480; }
            } else {
                if (i < 2048)      { srcb = Ah_; row = i >> 3;          soff = 0; }
                else               { srcb = Bh_; row = (i-2048) >> 3;   soff = 16384; }
            }
            int k4 = i & 7;
            const float* src = srcb + (size_t)row*ld + k0 + k4*4;
            uint32_t dst = sb + (uint32_t)(stg*STAGE_F + soff + row*32 + ((k4 ^ (row & 7)) << 2)) * 4u;
            cpa16(dst, src);
        }
        cpa_commit();
    };

    float acc[4][4][4];
    #pragma unroll
    for (int mi = 0; mi < 4; mi++)
        #pragma unroll
        for (int ni = 0; ni < 4; ni++)
            #pragma unroll
            for (int q = 0; q < 4; q++) acc[mi][ni][q] = 0.f;

    fill(0);

    for (int ck = 0; ck < nchunks; ck++) {
        if (ck + 1 < nchunks) { fill(ck + 1); cpa_wait<1>(); }
        else                  { cpa_wait<0>(); }
        __syncthreads();

        const float* S0 = smf + (ck & 1) * STAGE_F;
        const uint32_t* Sah = (const uint32_t*)(S0);
        const uint32_t* Sal = (const uint32_t*)(S0 + 8192);
        const uint32_t* Sbh = (const uint32_t*)(S0 + 16384);
        const uint32_t* Sbl = (const uint32_t*)(S0 + 20480);

        #pragma unroll
        for (int ks = 0; ks < 4; ks++) {
            const int p0 = ((2*ks)     ^ g)*4 + c;
            const int p1 = ((2*ks + 1) ^ g)*4 + c;
            uint32_t bh[4][2], bl[4][2];
            #pragma unroll
            for (int ni = 0; ni < 4; ni++) {
                int rn = (wn*32 + ni*8 + g) * 32;
                bh[ni][0] = Sbh[rn + p0];  bh[ni][1] = Sbh[rn + p1];
                if (NPASS == 3) { bl[ni][0] = Sbl[rn + p0];  bl[ni][1] = Sbl[rn + p1]; }
            }
            #pragma unroll
            for (int mi = 0; mi < 4; mi++) {
                int r0 = (wm*64 + mi*16 + g) * 32;
                uint32_t a0 = Sah[r0 + p0], a1 = Sah[r0 + 256 + p0];
                uint32_t a2 = Sah[r0 + p1], a3 = Sah[r0 + 256 + p1];
                uint32_t l0, l1, l2, l3;
                if (NPASS == 3) {
                    l0 = Sal[r0 + p0]; l1 = Sal[r0 + 256 + p0];
                    l2 = Sal[r0 + p1]; l3 = Sal[r0 + 256 + p1];
                }
                #pragma unroll
                for (int ni = 0; ni < 4; ni++) {
                    mma8(acc[mi][ni], a0, a1, a2, a3, bh[ni][0], bh[ni][1]);
                    if (NPASS == 3) {
                        mma8(acc[mi][ni], a0, a1, a2, a3, bl[ni][0], bl[ni][1]);
                        mma8(acc[mi][ni], l0, l1, l2, l3, bh[ni][0], bh[ni][1]);
                    }
                }
            }
        }
        __syncthreads();
    }

    // ------------- epilogue -------------
    #pragma unroll
    for (int mi = 0; mi < 4; mi++) {
        #pragma unroll
        for (int ni = 0; ni < 4; ni++) {
            const int r1 = m0 + wm*64 + mi*16 + g, r2 = r1 + 8;
            const int col = n0 + wn*32 + ni*8 + 2*c;
            float* a = acc[mi][ni];
            if (MODE == 0) {
                float2 bs = *(const float2*)(bias + col);
                float y0 = a[0] + bs.x, y1 = a[1] + bs.y;
                float y2 = a[2] + bs.x, y3 = a[3] + bs.y;
                float h0 = tf32_rna(y0), h1 = tf32_rna(y1);
                float h2 = tf32_rna(y2), h3 = tf32_rna(y3);
                *(float2*)(out0 + (size_t)r1*E + col) = make_float2(h0, h1);
                *(float2*)(out1 + (size_t)r1*E + col) = make_float2(y0 - h0, y1 - h1);
                *(float2*)(out0 + (size_t)r2*E + col) = make_float2(h2, h3);
                *(float2*)(out1 + (size_t)r2*E + col) = make_float2(y2 - h2, y3 - h3);
            } else if (MODE == 1) {
                float2 bs = *(const float2*)(bias + col);
                const size_t bo = (size_t)(m0 / T) * E * T;
                const int tl1 = (m0 % T) + wm*64 + mi*16 + g, tl2 = tl1 + 8;
                out0[bo + (size_t)col*T     + tl1] = tf32_rna(a[0] + bs.x);
                out0[bo + (size_t)(col+1)*T + tl1] = tf32_rna(a[1] + bs.y);
                out0[bo + (size_t)col*T     + tl2] = tf32_rna(a[2] + bs.x);
                out0[bo + (size_t)(col+1)*T + tl2] = tf32_rna(a[3] + bs.y);
            } else if (MODE == 2) {
                float* Sb = out0 + (size_t)b*T*T;
                *(float2*)(Sb + (size_t)r1*T + col) = make_float2(a[0], a[1]);
                *(float2*)(Sb + (size_t)r2*T + col) = make_float2(a[2], a[3]);
            } else {
                float* Ob = out0 + (size_t)b*T*E;
                *(float2*)(Ob + (size_t)r1*E + col) = make_float2(a[0], a[1]);
                *(float2*)(Ob + (size_t)r2*E + col) = make_float2(a[2], a[3]);
            }
        }
    }
}

// ------------------------- elementwise kernels -------------------------
__global__ void __launch_bounds__(256) splitk(
    const float* __restrict__ src, float* __restrict__ dh, float* __restrict__ dl, int n4)
{
    int i = blockIdx.x * 256 + threadIdx.x;
    if (i >= n4) return;
    float4 v = ((const float4*)src)[i];
    float4 h, l;
    h.x = tf32_rna(v.x); l.x = v.x - h.x;
    h.y = tf32_rna(v.y); l.y = v.y - h.y;
    h.z = tf32_rna(v.z); l.z = v.z - h.z;
    h.w = tf32_rna(v.w); l.w = v.w - h.w;
    ((float4*)dh)[i] = h;
    ((float4*)dl)[i] = l;
}

// per-key-column j stats over i>=j (softmax over QUERY axis quirk)
__global__ void __launch_bounds__(256) colstats()
{
    const int bb = blockIdx.y;
    const int j0 = blockIdx.x * 32;
    const int c = threadIdx.x & 31, r = threadIdx.x >> 5;
    const int j = j0 + c;
    const float* S = g_S + (size_t)bb*T*T;
    float m = -INFINITY, l = 0.f;
    for (int i = j0 + r; i < T; i += 8) {
        float v = S[(size_t)i*T + j];
        if (i >= j) {
            if (v <= m) l += __expf(v - m);
            else { l = l * __expf(m - v) + 1.f; m = v; }
        }
    }
    __shared__ float sm_[8][33], sl_[8][33];
    sm_[r][c] = m; sl_[r][c] = l;
    __syncthreads();
    if (r == 0) {
        float M = m, L = l;
        #pragma unroll
        for (int rr = 1; rr < 8; rr++) {
            float m2 = sm_[rr][c], l2 = sl_[rr][c];
            if (m2 > M) { L = L * __expf(M - m2) + l2; M = m2; }
            else if (l2 > 0.f) L += l2 * __expf(m2 - M);
        }
        g_M [bb*T + j] = M;
        g_Li[bb*T + j] = 1.f / L;
    }
}

// P[i,j] = exp(S[i,j]-m_j)*linv_j for j<=i else 0 (tf32-rounded).
// Also zero-fills tiles (it, it+1) for even it, so the 256-row out-GEMM
// reads a fully-initialized rectangular P region.
__global__ void __launch_bounds__(256) psplit()
{
    const int jt = blockIdx.x, it = blockIdx.y;
    const int bb = blockIdx.z;
    const size_t base = (size_t)bb*T*T;
    const int i0 = it*128, j0 = jt*128;
    if (jt > it) {
        if (jt == it + 1 && (it & 1) == 0) {
            for (int idx = threadIdx.x; idx < 128*32; idx += 256) {
                int rr = idx >> 5, c4 = idx & 31;
                *(float4*)(g_Ph + base + (size_t)(i0+rr)*T + j0 + c4*4) =
                    make_float4(0.f, 0.f, 0.f, 0.f);
            }
        }
        return;
    }
    for (int idx = threadIdx.x; idx < 128*32; idx += 256) {
        int rr = idx >> 5, c4 = idx & 31;
        int i = i0 + rr, j = j0 + c4*4;
        float4 s = *(const float4*)(g_S + base + (size_t)i*T + j);
        float sv[4] = {s.x, s.y, s.z, s.w};
        float h[4];
        #pragma unroll
        for (int q = 0; q < 4; q++) {
            int jj = j + q;
            float p = (jj <= i) ? __expf(sv[q] - g_M[bb*T + jj]) * g_Li[bb*T + jj] : 0.f;
            h[q] = tf32_rna(p);
        }
        *(float4*)(g_Ph + base + (size_t)i*T + j) = make_float4(h[0], h[1], h[2], h[3]);
    }
}

// ------------------------- host -------------------------
extern "C" void kernel_launch(void* const* d_in, const int* in_sizes, int n_in,
                              void* d_out, int out_size)
{
    const float* x_emb = (const float*)d_in[0];
    const float* Wk = (const float*)d_in[2];
    const float* bk = (const float*)d_in[3];
    const float* Wq = (const float*)d_in[4];
    const float* bq = (const float*)d_in[5];
    const float* Wv = (const float*)d_in[6];
    const float* bv = (const float*)d_in[7];
    float* out = (float*)d_out;

    void *Xh,*Xl,*Whk,*Wlk,*Whq,*Wlq,*Whv,*Wlv,*Qh,*Ql,*Kh,*Kl,*Vth,*Sp,*Ph;
    cudaGetSymbolAddress(&Xh, g_Xh);   cudaGetSymbolAddress(&Xl, g_Xl);
    cudaGetSymbolAddress(&Whk, g_Whk); cudaGetSymbolAddress(&Wlk, g_Wlk);
    cudaGetSymbolAddress(&Whq, g_Whq); cudaGetSymbolAddress(&Wlq, g_Wlq);
    cudaGetSymbolAddress(&Whv, g_Whv); cudaGetSymbolAddress(&Wlv, g_Wlv);
    cudaGetSymbolAddress(&Qh, g_Qh);   cudaGetSymbolAddress(&Ql, g_Ql);
    cudaGetSymbolAddress(&Kh, g_Kh);   cudaGetSymbolAddress(&Kl, g_Kl);
    cudaGetSymbolAddress(&Vth, g_Vth);
    cudaGetSymbolAddress(&Sp, g_S);    cudaGetSymbolAddress(&Ph, g_Ph);

    cudaFuncSetAttribute(gemm_mma<0>, cudaFuncAttributeMaxDynamicSharedMemorySize, SMEM_BYTES);
    cudaFuncSetAttribute(gemm_mma<1>, cudaFuncAttributeMaxDynamicSharedMemorySize, SMEM_BYTES);
    cudaFuncSetAttribute(gemm_mma<2>, cudaFuncAttributeMaxDynamicSharedMemorySize, SMEM_BYTES);
    cudaFuncSetAttribute(gemm_mma<3>, cudaFuncAttributeMaxDynamicSharedMemorySize, SMEM_BYTES);

    // 1. tf32 hi/lo splits
    splitk<<<(MT*E/4 + 255)/256, 256>>>(x_emb, (float*)Xh, (float*)Xl, MT*E/4);
    splitk<<<(E*E/4 + 255)/256, 256>>>(Wk, (float*)Whk, (float*)Wlk, E*E/4);
    splitk<<<(E*E/4 + 255)/256, 256>>>(Wq, (float*)Whq, (float*)Wlq, E*E/4);
    splitk<<<(E*E/4 + 255)/256, 256>>>(Wv, (float*)Whv, (float*)Wlv, E*E/4);

    // 2. projections
    dim3 gp(E/128, MT/256);
    gemm_mma<0><<<gp, 512, SMEM_BYTES>>>((float*)Xh, (float*)Xl, (float*)Whq, (float*)Wlq,
                                         (float*)Qh, (float*)Ql, bq);
    gemm_mma<0><<<gp, 512, SMEM_BYTES>>>((float*)Xh, (float*)Xl, (float*)Whk, (float*)Wlk,
                                         (float*)Kh, (float*)Kl, bk);
    gemm_mma<1><<<gp, 512, SMEM_BYTES>>>((float*)Xh, (float*)Xl, (float*)Whv, (float*)Wlv,
                                         (float*)Vth, nullptr, bv);

    // 3. scores (lower triangle at 256-row granularity)
    dim3 gs(T/128, T/256, NB);
    gemm_mma<2><<<gs, 512, SMEM_BYTES>>>((float*)Qh, (float*)Ql, (float*)Kh, (float*)Kl,
                                         (float*)Sp, nullptr, nullptr);

    // 4. column softmax stats + P build (with zero padding tiles)
    dim3 gc(T/32, NB);
    colstats<<<gc, 256>>>();
    psplit<<<dim3(T/128, T/128, NB), 256>>>();

    // 5. output gemm
    dim3 go(E/128, T/256, NB);
    gemm_mma<3><<<go, 512, SMEM_BYTES>>>((float*)Ph, nullptr, (float*)Vth, nullptr,
                                         out, nullptr, nullptr);
}

// round 8
// speedup vs baseline: 2.5840x; 1.4243x over previous
#include <cuda_runtime.h>
#include <cuda_bf16.h>
#include <math.h>
#include <stdint.h>

#define NB 8
#define T  2048
#define E  1024
#define MT (NB*T)

typedef __nv_bfloat16 bf16;

// ------------------------- scratch (device globals) -------------------------
__device__ bf16 g_Xbh[(size_t)MT*E], g_Xbl[(size_t)MT*E];
__device__ bf16 g_Wqh[(size_t)E*E], g_Wql[(size_t)E*E];
__device__ bf16 g_Wkh[(size_t)E*E], g_Wkl[(size_t)E*E];
__device__ bf16 g_Wvh[(size_t)E*E], g_Wvl[(size_t)E*E];
__device__ bf16 g_Qbh[(size_t)MT*E], g_Qbl[(size_t)MT*E];
__device__ bf16 g_Kbh[(size_t)MT*E], g_Kbl[(size_t)MT*E];
__device__ float g_Vth[(size_t)NB*E*T];          // [b][f][t], tf32-rounded
__device__ float g_S [(size_t)NB*T*T];
__device__ float g_Ph[(size_t)NB*T*T];
__device__ float g_M[NB*T], g_Li[NB*T];

// ------------------------- helpers -------------------------
__device__ __forceinline__ uint32_t smem_u32(const void* p) {
    uint32_t a;
    asm("{ .reg .u64 t; cvta.to.shared.u64 t, %1; cvt.u32.u64 %0, t; }" : "=r"(a) : "l"(p));
    return a;
}
__device__ __forceinline__ float tf32_rna(float x) {
    uint32_t u; asm("cvt.rna.tf32.f32 %0, %1;" : "=r"(u) : "f"(x));
    return __uint_as_float(u);
}
__device__ __forceinline__ void cpa16(uint32_t dst, const void* src) {
    asm volatile("cp.async.cg.shared.global [%0], [%1], 16;" :: "r"(dst), "l"(src) : "memory");
}
__device__ __forceinline__ void cpa_commit() { asm volatile("cp.async.commit_group;" ::: "memory"); }
template<int N> __device__ __forceinline__ void cpa_wait() {
    asm volatile("cp.async.wait_group %0;" :: "n"(N) : "memory");
}
__device__ __forceinline__ void mma16(float* d, uint32_t a0, uint32_t a1, uint32_t a2, uint32_t a3,
                                      uint32_t b0, uint32_t b1) {
    asm volatile("mma.sync.aligned.m16n8k16.row.col.f32.bf16.bf16.f32 "
                 "{%0,%1,%2,%3},{%4,%5,%6,%7},{%8,%9},{%0,%1,%2,%3};"
                 : "+f"(d[0]), "+f"(d[1]), "+f"(d[2]), "+f"(d[3])
                 : "r"(a0), "r"(a1), "r"(a2), "r"(a3), "r"(b0), "r"(b1));
}
__device__ __forceinline__ void mma8(float* d, uint32_t a0, uint32_t a1, uint32_t a2, uint32_t a3,
                                     uint32_t b0, uint32_t b1) {
    asm volatile("mma.sync.aligned.m16n8k8.row.col.f32.tf32.tf32.f32 "
                 "{%0,%1,%2,%3},{%4,%5,%6,%7},{%8,%9},{%0,%1,%2,%3};"
                 : "+f"(d[0]), "+f"(d[1]), "+f"(d[2]), "+f"(d[3])
                 : "r"(a0), "r"(a1), "r"(a2), "r"(a3), "r"(b0), "r"(b1));
}
__device__ __forceinline__ uint32_t pack_bf2(float x, float y) {
    bf16 hx = __float2bfloat16(x), hy = __float2bfloat16(y);
    uint16_t ux = *(uint16_t*)&hx, uy = *(uint16_t*)&hy;
    uint32_t r;
    asm("mov.b32 %0, {%1, %2};" : "=r"(r) : "h"(ux), "h"(uy));
    return r;
}

// ============================================================
// bf16x2 3-pass GEMM: D = sum_k A[m,k]*B[n,k], 256x128x32, 512 thr, 3-stage
// MODE 0: proj Q/K  (+bias, bf16 hi/lo split row-major store)
// MODE 1: proj V    (+bias, tf32-rounded fp32 TRANSPOSED store -> Vt[b][f][t])
// MODE 2: scores    (triangle grid, fp32 store to S)
// ============================================================
#define BSTAGE_E 24576
#define BSMEM_BYTES (3*BSTAGE_E*2)      // 147456

template<int MODE>
__global__ void __launch_bounds__(512, 1) gemm_bf16(
    const bf16* __restrict__ pAh, const bf16* __restrict__ pAl,
    const bf16* __restrict__ pBh, const bf16* __restrict__ pBl,
    float* __restrict__ outf, bf16* __restrict__ oh, bf16* __restrict__ ol,
    const float* __restrict__ bias)
{
    const int m0 = blockIdx.y * 256, n0 = blockIdx.x * 128;
    if (MODE == 2 && n0 >= m0 + 256) return;

    extern __shared__ bf16 smb[];
    const uint32_t sb = smem_u32(smb);
    const int tid = threadIdx.x;
    const int lane = tid & 31, warp = tid >> 5;
    const int wm = warp >> 2, wn = warp & 3;
    const int g = lane >> 2, c = lane & 3;
    const int b = blockIdx.z;

    const bf16 *Ah_, *Al_, *Bh_, *Bl_;
    if (MODE == 2) {
        Ah_ = pAh + (size_t)(b*T + m0)*E;  Al_ = pAl + (size_t)(b*T + m0)*E;
        Bh_ = pBh + (size_t)(b*T + n0)*E;  Bl_ = pBl + (size_t)(b*T + n0)*E;
    } else {
        Ah_ = pAh + (size_t)m0*E;  Al_ = pAl + (size_t)m0*E;
        Bh_ = pBh + (size_t)n0*E;  Bl_ = pBl + (size_t)n0*E;
    }
    const int nchunks = E/32;

    auto fill = [&](int ck) {
        const int stg = ck % 3;
        const int k0 = ck * 32;
        for (int i = tid; i < 3072; i += 512) {
            const bf16* srcb; int row; uint32_t soff;
            if (i < 1024)      { srcb = Ah_; row = i >> 2;          soff = 0; }
            else if (i < 2048) { srcb = Al_; row = (i-1024) >> 2;   soff = 8192; }
            else if (i < 2560) { srcb = Bh_; row = (i-2048) >> 2;   soff = 16384; }
            else               { srcb = Bl_; row = (i-2560) >> 2;   soff = 20480; }
            const int seg = i & 3;
            const uint32_t wrd = (uint32_t)((seg << 2) ^ (((row >> 1) & 3) << 2));
            uint32_t dst = sb + (uint32_t)(stg*BSTAGE_E + soff + row*32 + wrd*2) * 2u;
            cpa16(dst, srcb + (size_t)row*E + k0 + seg*8);
        }
        cpa_commit();
    };

    float acc[4][4][4];
    #pragma unroll
    for (int mi = 0; mi < 4; mi++)
        #pragma unroll
        for (int ni = 0; ni < 4; ni++)
            #pragma unroll
            for (int q = 0; q < 4; q++) acc[mi][ni][q] = 0.f;

    fill(0);
    fill(1);

    for (int ck = 0; ck < nchunks; ck++) {
        if (ck + 1 < nchunks) cpa_wait<1>(); else cpa_wait<0>();
        __syncthreads();
        if (ck + 2 < nchunks) fill(ck + 2);

        const bf16* S0 = smb + (ck % 3) * BSTAGE_E;
        const uint32_t* SAh = (const uint32_t*)(S0);
        const uint32_t* SAl = (const uint32_t*)(S0 + 8192);
        const uint32_t* SBh = (const uint32_t*)(S0 + 16384);
        const uint32_t* SBl = (const uint32_t*)(S0 + 20480);

        #pragma unroll
        for (int ks = 0; ks < 2; ks++) {
            const int w0 = 8*ks + c, w1 = w0 + 4;
            uint32_t bh[4][2], bl[4][2];
            #pragma unroll
            for (int ni = 0; ni < 4; ni++) {
                const int rn = wn*32 + ni*8 + g;
                const int sw = ((rn >> 1) & 3) << 2;
                bh[ni][0] = SBh[rn*16 + (w0^sw)];  bh[ni][1] = SBh[rn*16 + (w1^sw)];
                bl[ni][0] = SBl[rn*16 + (w0^sw)];  bl[ni][1] = SBl[rn*16 + (w1^sw)];
            }
            #pragma unroll
            for (int mi = 0; mi < 4; mi++) {
                const int r1 = wm*64 + mi*16 + g, r2 = r1 + 8;
                const int sw = ((r1 >> 1) & 3) << 2;
                uint32_t a0 = SAh[r1*16 + (w0^sw)], a1 = SAh[r2*16 + (w0^sw)];
                uint32_t a2 = SAh[r1*16 + (w1^sw)], a3 = SAh[r2*16 + (w1^sw)];
                uint32_t l0 = SAl[r1*16 + (w0^sw)], l1 = SAl[r2*16 + (w0^sw)];
                uint32_t l2 = SAl[r1*16 + (w1^sw)], l3 = SAl[r2*16 + (w1^sw)];
                #pragma unroll
                for (int ni = 0; ni < 4; ni++) {
                    mma16(acc[mi][ni], a0, a1, a2, a3, bh[ni][0], bh[ni][1]);
                    mma16(acc[mi][ni], a0, a1, a2, a3, bl[ni][0], bl[ni][1]);
                    mma16(acc[mi][ni], l0, l1, l2, l3, bh[ni][0], bh[ni][1]);
                }
            }
        }
    }

    #pragma unroll
    for (int mi = 0; mi < 4; mi++) {
        #pragma unroll
        for (int ni = 0; ni < 4; ni++) {
            const int r1 = m0 + wm*64 + mi*16 + g, r2 = r1 + 8;
            const int col = n0 + wn*32 + ni*8 + 2*c;
            float* a = acc[mi][ni];
            if (MODE == 0) {
                float2 bs = *(const float2*)(bias + col);
                float y0 = a[0] + bs.x, y1 = a[1] + bs.y;
                float y2 = a[2] + bs.x, y3 = a[3] + bs.y;
                float h0 = __bfloat162float(__float2bfloat16(y0));
                float h1 = __bfloat162float(__float2bfloat16(y1));
                float h2 = __bfloat162float(__float2bfloat16(y2));
                float h3 = __bfloat162float(__float2bfloat16(y3));
                *(uint32_t*)(oh + (size_t)r1*E + col) = pack_bf2(y0, y1);
                *(uint32_t*)(ol + (size_t)r1*E + col) = pack_bf2(y0 - h0, y1 - h1);
                *(uint32_t*)(oh + (size_t)r2*E + col) = pack_bf2(y2, y3);
                *(uint32_t*)(ol + (size_t)r2*E + col) = pack_bf2(y2 - h2, y3 - h3);
            } else if (MODE == 1) {
                float2 bs = *(const float2*)(bias + col);
                const size_t bo = (size_t)(m0 / T) * E * T;
                const int tl1 = (m0 % T) + wm*64 + mi*16 + g, tl2 = tl1 + 8;
                outf[bo + (size_t)col*T     + tl1] = tf32_rna(a[0] + bs.x);
                outf[bo + (size_t)(col+1)*T + tl1] = tf32_rna(a[1] + bs.y);
                outf[bo + (size_t)col*T     + tl2] = tf32_rna(a[2] + bs.x);
                outf[bo + (size_t)(col+1)*T + tl2] = tf32_rna(a[3] + bs.y);
            } else {
                float* Sb = outf + (size_t)b*T*T;
                *(float2*)(Sb + (size_t)r1*T + col) = make_float2(a[0], a[1]);
                *(float2*)(Sb + (size_t)r2*T + col) = make_float2(a[2], a[3]);
            }
        }
    }
}

// ============================================================
// out GEMM: O = P @ Vt^T, tf32 1-pass, 256x128x32, 2-stage
// ============================================================
#define STAGE_F 24576
#define SMEM_BYTES (2*STAGE_F*4)

__global__ void __launch_bounds__(512, 1) gemm_out(
    const float* __restrict__ pA, const float* __restrict__ pB,
    float* __restrict__ out0)
{
    const int m0 = blockIdx.y * 256, n0 = blockIdx.x * 128;
    extern __shared__ float smf[];
    const uint32_t sb = smem_u32(smf);
    const int tid = threadIdx.x;
    const int lane = tid & 31, warp = tid >> 5;
    const int wm = warp >> 2, wn = warp & 3;
    const int g = lane >> 2, c = lane & 3;
    const int b = blockIdx.z;

    const int nchunks = m0/32 + 8;
    const float* A_ = pA + (size_t)b*T*T + (size_t)m0*T;
    const float* B_ = pB + ((size_t)b*E + n0)*T;

    auto fill = [&](int ck) {
        const int stg = ck & 1;
        const int k0 = ck * 32;
        for (int i = tid; i < 3072; i += 512) {
            const float* srcb; int row; uint32_t soff;
            if (i < 2048) { srcb = A_; row = i >> 3;        soff = 0; }
            else          { srcb = B_; row = (i-2048) >> 3; soff = 16384; }
            int k4 = i & 7;
            uint32_t dst = sb + (uint32_t)(stg*STAGE_F + soff + row*32 + ((k4 ^ (row & 7)) << 2)) * 4u;
            cpa16(dst, srcb + (size_t)row*T + k0 + k4*4);
        }
        cpa_commit();
    };

    float acc[4][4][4];
    #pragma unroll
    for (int mi = 0; mi < 4; mi++)
        #pragma unroll
        for (int ni = 0; ni < 4; ni++)
            #pragma unroll
            for (int q = 0; q < 4; q++) acc[mi][ni][q] = 0.f;

    fill(0);

    for (int ck = 0; ck < nchunks; ck++) {
        if (ck + 1 < nchunks) { fill(ck + 1); cpa_wait<1>(); }
        else                  { cpa_wait<0>(); }
        __syncthreads();

        const float* S0 = smf + (ck & 1) * STAGE_F;
        const uint32_t* Sa = (const uint32_t*)(S0);
        const uint32_t* Sv = (const uint32_t*)(S0 + 16384);

        #pragma unroll
        for (int ks = 0; ks < 4; ks++) {
            const int p0 = ((2*ks)     ^ g)*4 + c;
            const int p1 = ((2*ks + 1) ^ g)*4 + c;
            uint32_t bh[4][2];
            #pragma unroll
            for (int ni = 0; ni < 4; ni++) {
                int rn = (wn*32 + ni*8 + g) * 32;
                bh[ni][0] = Sv[rn + p0];  bh[ni][1] = Sv[rn + p1];
            }
            #pragma unroll
            for (int mi = 0; mi < 4; mi++) {
                int r0 = (wm*64 + mi*16 + g) * 32;
                uint32_t a0 = Sa[r0 + p0], a1 = Sa[r0 + 256 + p0];
                uint32_t a2 = Sa[r0 + p1], a3 = Sa[r0 + 256 + p1];
                #pragma unroll
                for (int ni = 0; ni < 4; ni++)
                    mma8(acc[mi][ni], a0, a1, a2, a3, bh[ni][0], bh[ni][1]);
            }
        }
        __syncthreads();
    }

    #pragma unroll
    for (int mi = 0; mi < 4; mi++) {
        #pragma unroll
        for (int ni = 0; ni < 4; ni++) {
            const int r1 = m0 + wm*64 + mi*16 + g, r2 = r1 + 8;
            const int col = n0 + wn*32 + ni*8 + 2*c;
            float* a = acc[mi][ni];
            float* Ob = out0 + (size_t)b*T*E;
            *(float2*)(Ob + (size_t)r1*E + col) = make_float2(a[0], a[1]);
            *(float2*)(Ob + (size_t)r2*E + col) = make_float2(a[2], a[3]);
        }
    }
}

// ------------------------- elementwise kernels -------------------------
__global__ void __launch_bounds__(256) splitk_bf(
    const float* __restrict__ src, bf16* __restrict__ dh, bf16* __restrict__ dl, int n4)
{
    int i = blockIdx.x * 256 + threadIdx.x;
    if (i >= n4) return;
    float4 v = ((const float4*)src)[i];
    uint32_t h0 = pack_bf2(v.x, v.y), h1 = pack_bf2(v.z, v.w);
    float r0 = v.x - __bfloat162float(__float2bfloat16(v.x));
    float r1 = v.y - __bfloat162float(__float2bfloat16(v.y));
    float r2 = v.z - __bfloat162float(__float2bfloat16(v.z));
    float r3 = v.w - __bfloat162float(__float2bfloat16(v.w));
    uint32_t l0 = pack_bf2(r0, r1), l1 = pack_bf2(r2, r3);
    ((uint2*)dh)[i] = make_uint2(h0, h1);
    ((uint2*)dl)[i] = make_uint2(l0, l1);
}

__global__ void __launch_bounds__(256) colstats()
{
    const int bb = blockIdx.y;
    const int j0 = blockIdx.x * 32;
    const int c = threadIdx.x & 31, r = threadIdx.x >> 5;
    const int j = j0 + c;
    const float* S = g_S + (size_t)bb*T*T;
    float m = -INFINITY, l = 0.f;
    for (int i = j0 + r; i < T; i += 8) {
        float v = S[(size_t)i*T + j];
        if (i >= j) {
            if (v <= m) l += __expf(v - m);
            else { l = l * __expf(m - v) + 1.f; m = v; }
        }
    }
    __shared__ float sm_[8][33], sl_[8][33];
    sm_[r][c] = m; sl_[r][c] = l;
    __syncthreads();
    if (r == 0) {
        float M = m, L = l;
        #pragma unroll
        for (int rr = 1; rr < 8; rr++) {
            float m2 = sm_[rr][c], l2 = sl_[rr][c];
            if (m2 > M) { L = L * __expf(M - m2) + l2; M = m2; }
            else if (l2 > 0.f) L += l2 * __expf(m2 - M);
        }
        g_M [bb*T + j] = M;
        g_Li[bb*T + j] = 1.f / L;
    }
}

__global__ void __launch_bounds__(256) psplit()
{
    const int jt = blockIdx.x, it = blockIdx.y;
    const int bb = blockIdx.z;
    const size_t base = (size_t)bb*T*T;
    const int i0 = it*128, j0 = jt*128;
    if (jt > it) {
        if (jt == it + 1 && (it & 1) == 0) {
            for (int idx = threadIdx.x; idx < 128*32; idx += 256) {
                int rr = idx >> 5, c4 = idx & 31;
                *(float4*)(g_Ph + base + (size_t)(i0+rr)*T + j0 + c4*4) =
                    make_float4(0.f, 0.f, 0.f, 0.f);
            }
        }
        return;
    }
    for (int idx = threadIdx.x; idx < 128*32; idx += 256) {
        int rr = idx >> 5, c4 = idx & 31;
        int i = i0 + rr, j = j0 + c4*4;
        float4 s = *(const float4*)(g_S + base + (size_t)i*T + j);
        float sv[4] = {s.x, s.y, s.z, s.w};
        float h[4];
        #pragma unroll
        for (int q = 0; q < 4; q++) {
            int jj = j + q;
            float p = (jj <= i) ? __expf(sv[q] - g_M[bb*T + jj]) * g_Li[bb*T + jj] : 0.f;
            h[q] = tf32_rna(p);
        }
        *(float4*)(g_Ph + base + (size_t)i*T + j) = make_float4(h[0], h[1], h[2], h[3]);
    }
}

// ------------------------- host -------------------------
extern "C" void kernel_launch(void* const* d_in, const int* in_sizes, int n_in,
                              void* d_out, int out_size)
{
    const float* x_emb = (const float*)d_in[0];
    const float* Wk = (const float*)d_in[2];
    const float* bk = (const float*)d_in[3];
    const float* Wq = (const float*)d_in[4];
    const float* bq = (const float*)d_in[5];
    const float* Wv = (const float*)d_in[6];
    const float* bv = (const float*)d_in[7];
    float* out = (float*)d_out;

    void *Xbh,*Xbl,*Wqh,*Wql,*Wkh,*Wkl,*Wvh,*Wvl,*Qbh,*Qbl,*Kbh,*Kbl,*Vth,*Sp,*Ph;
    cudaGetSymbolAddress(&Xbh, g_Xbh); cudaGetSymbolAddress(&Xbl, g_Xbl);
    cudaGetSymbolAddress(&Wqh, g_Wqh); cudaGetSymbolAddress(&Wql, g_Wql);
    cudaGetSymbolAddress(&Wkh, g_Wkh); cudaGetSymbolAddress(&Wkl, g_Wkl);
    cudaGetSymbolAddress(&Wvh, g_Wvh); cudaGetSymbolAddress(&Wvl, g_Wvl);
    cudaGetSymbolAddress(&Qbh, g_Qbh); cudaGetSymbolAddress(&Qbl, g_Qbl);
    cudaGetSymbolAddress(&Kbh, g_Kbh); cudaGetSymbolAddress(&Kbl, g_Kbl);
    cudaGetSymbolAddress(&Vth, g_Vth);
    cudaGetSymbolAddress(&Sp, g_S);    cudaGetSymbolAddress(&Ph, g_Ph);

    cudaFuncSetAttribute(gemm_bf16<0>, cudaFuncAttributeMaxDynamicSharedMemorySize, BSMEM_BYTES);
    cudaFuncSetAttribute(gemm_bf16<1>, cudaFuncAttributeMaxDynamicSharedMemorySize, BSMEM_BYTES);
    cudaFuncSetAttribute(gemm_bf16<2>, cudaFuncAttributeMaxDynamicSharedMemorySize, BSMEM_BYTES);
    cudaFuncSetAttribute(gemm_out,     cudaFuncAttributeMaxDynamicSharedMemorySize, SMEM_BYTES);

    splitk_bf<<<(MT*E/4 + 255)/256, 256>>>(x_emb, (bf16*)Xbh, (bf16*)Xbl, MT*E/4);
    splitk_bf<<<(E*E/4 + 255)/256, 256>>>(Wq, (bf16*)Wqh, (bf16*)Wql, E*E/4);
    splitk_bf<<<(E*E/4 + 255)/256, 256>>>(Wk, (bf16*)Wkh, (bf16*)Wkl, E*E/4);
    splitk_bf<<<(E*E/4 + 255)/256, 256>>>(Wv, (bf16*)Wvh, (bf16*)Wvl, E*E/4);

    dim3 gp(E/128, MT/256);
    gemm_bf16<0><<<gp, 512, BSMEM_BYTES>>>((bf16*)Xbh, (bf16*)Xbl, (bf16*)Wqh, (bf16*)Wql,
                                           nullptr, (bf16*)Qbh, (bf16*)Qbl, bq);
    gemm_bf16<0><<<gp, 512, BSMEM_BYTES>>>((bf16*)Xbh, (bf16*)Xbl, (bf16*)Wkh, (bf16*)Wkl,
                                           nullptr, (bf16*)Kbh, (bf16*)Kbl, bk);
    gemm_bf16<1><<<gp, 512, BSMEM_BYTES>>>((bf16*)Xbh, (bf16*)Xbl, (bf16*)Wvh, (bf16*)Wvl,
                                           (float*)Vth, nullptr, nullptr, bv);

    dim3 gs(T/128, T/256, NB);
    gemm_bf16<2><<<gs, 512, BSMEM_BYTES>>>((bf16*)Qbh, (bf16*)Qbl, (bf16*)Kbh, (bf16*)Kbl,
                                           (float*)Sp, nullptr, nullptr, nullptr);

    dim3 gc(T/32, NB);
    colstats<<<gc, 256>>>();
    psplit<<<dim3(T/128, T/128, NB), 256>>>();

    dim3 go(E/128, T/256, NB);
    gemm_out<<<go, 512, SMEM_BYTES>>>((float*)Ph, (float*)Vth, out);
}